// round 8
// baseline (speedup 1.0000x reference)
#include <cuda_runtime.h>
#include <math.h>
#include <stdint.h>

#define BATCH   2
#define T_SEQ   2048
#define CDIM    1024
#define HEADS   16
#define DHEAD   64
#define C3      3072
#define MROWS   4096

typedef unsigned long long ull;

__device__ float g_qkv[(size_t)MROWS * C3];   // 48 MB
__device__ float g_y  [(size_t)MROWS * CDIM]; // 16 MB

// ---- packed f32x2 helpers (FFMA2 — HW double-rate fp32, PTX-only) ----------
__device__ __forceinline__ void fma2(ull& d, ull a, ull b) {
    asm("fma.rn.f32x2 %0, %1, %2, %0;" : "+l"(d) : "l"(a), "l"(b));
}
__device__ __forceinline__ ull mul2(ull a, ull b) {
    ull r; asm("mul.rn.f32x2 %0, %1, %2;" : "=l"(r) : "l"(a), "l"(b)); return r;
}
__device__ __forceinline__ ull pack2(float x, float y) {
    ull r; asm("mov.b64 %0, {%1, %2};" : "=l"(r) : "f"(x), "f"(y)); return r;
}
__device__ __forceinline__ float2 unpack2(ull v) {
    float2 r; asm("mov.b64 {%0, %1}, %2;" : "=f"(r.x), "=f"(r.y) : "l"(v)); return r;
}
__device__ __forceinline__ void cpasync16(uint32_t s, const void* g) {
    asm volatile("cp.async.cg.shared.global [%0], [%1], 16;" :: "r"(s), "l"(g));
}

// ---------------------------------------------------------------------------
// NT GEMM: C[M,N] = A[M,K] * B[N,K]^T, 128x128 tile, BK=16, 256 thr, 8x8/thr.
// Double-buffered SMEM + register prefetch; inner product in fma.rn.f32x2.
// ---------------------------------------------------------------------------
__global__ void __launch_bounds__(256)
gemm_nt_kernel(const float* __restrict__ A,
               const float* __restrict__ B,
               float* __restrict__ C,
               int M, int N, int K)
{
    const int BK = 16;
    __shared__ __align__(16) float As[2][16][132];
    __shared__ __align__(16) float Bs[2][16][132];

    const int t  = threadIdx.x;
    const int tx = t % 16;
    const int ty = t / 16;
    const int m0 = blockIdx.y * 128;
    const int n0 = blockIdx.x * 128;

    int lrow[2], lc4[2];
    #pragma unroll
    for (int i = 0; i < 2; i++) { int idx = t + i * 256; lrow[i] = idx >> 2; lc4[i] = idx & 3; }

    ull acc[8][4];
    #pragma unroll
    for (int i = 0; i < 8; i++)
        #pragma unroll
        for (int j = 0; j < 4; j++) acc[i][j] = 0ull;

    #pragma unroll
    for (int i = 0; i < 2; i++) {
        float4 va = *(const float4*)&A[(size_t)(m0 + lrow[i]) * K + lc4[i] * 4];
        float4 vb = *(const float4*)&B[(size_t)(n0 + lrow[i]) * K + lc4[i] * 4];
        As[0][lc4[i]*4+0][lrow[i]] = va.x; As[0][lc4[i]*4+1][lrow[i]] = va.y;
        As[0][lc4[i]*4+2][lrow[i]] = va.z; As[0][lc4[i]*4+3][lrow[i]] = va.w;
        Bs[0][lc4[i]*4+0][lrow[i]] = vb.x; Bs[0][lc4[i]*4+1][lrow[i]] = vb.y;
        Bs[0][lc4[i]*4+2][lrow[i]] = vb.z; Bs[0][lc4[i]*4+3][lrow[i]] = vb.w;
    }
    __syncthreads();

    const int nt = K / BK;
    for (int tt = 0; tt < nt; tt++) {
        float4 pa[2], pb[2];
        const bool has_next = (tt + 1 < nt);
        if (has_next) {
            const int kn = (tt + 1) * BK;
            #pragma unroll
            for (int i = 0; i < 2; i++) {
                pa[i] = *(const float4*)&A[(size_t)(m0 + lrow[i]) * K + kn + lc4[i] * 4];
                pb[i] = *(const float4*)&B[(size_t)(n0 + lrow[i]) * K + kn + lc4[i] * 4];
            }
        }

        const float (*Ac)[132] = As[tt & 1];
        const float (*Bc)[132] = Bs[tt & 1];
        #pragma unroll
        for (int kk = 0; kk < BK; kk++) {
            float4 a0 = *(const float4*)&Ac[kk][ty * 8];
            float4 a1 = *(const float4*)&Ac[kk][ty * 8 + 4];
            ulonglong2 b0 = *(const ulonglong2*)&Bc[kk][tx * 8];
            ulonglong2 b1 = *(const ulonglong2*)&Bc[kk][tx * 8 + 4];
            ull bp[4] = { b0.x, b0.y, b1.x, b1.y };
            ull ad[8] = { pack2(a0.x, a0.x), pack2(a0.y, a0.y),
                          pack2(a0.z, a0.z), pack2(a0.w, a0.w),
                          pack2(a1.x, a1.x), pack2(a1.y, a1.y),
                          pack2(a1.z, a1.z), pack2(a1.w, a1.w) };
            #pragma unroll
            for (int i = 0; i < 8; i++)
                #pragma unroll
                for (int j = 0; j < 4; j++)
                    fma2(acc[i][j], ad[i], bp[j]);
        }

        if (has_next) {
            const int nb = (tt + 1) & 1;
            #pragma unroll
            for (int i = 0; i < 2; i++) {
                As[nb][lc4[i]*4+0][lrow[i]] = pa[i].x; As[nb][lc4[i]*4+1][lrow[i]] = pa[i].y;
                As[nb][lc4[i]*4+2][lrow[i]] = pa[i].z; As[nb][lc4[i]*4+3][lrow[i]] = pa[i].w;
                Bs[nb][lc4[i]*4+0][lrow[i]] = pb[i].x; Bs[nb][lc4[i]*4+1][lrow[i]] = pb[i].y;
                Bs[nb][lc4[i]*4+2][lrow[i]] = pb[i].z; Bs[nb][lc4[i]*4+3][lrow[i]] = pb[i].w;
            }
            __syncthreads();
        }
    }

    #pragma unroll
    for (int i = 0; i < 8; i++) {
        size_t off = (size_t)(m0 + ty * 8 + i) * N + n0 + tx * 8;
        float2 c0 = unpack2(acc[i][0]), c1 = unpack2(acc[i][1]);
        float2 c2 = unpack2(acc[i][2]), c3 = unpack2(acc[i][3]);
        *(float4*)&C[off]     = make_float4(c0.x, c0.y, c1.x, c1.y);
        *(float4*)&C[off + 4] = make_float4(c2.x, c2.y, c3.x, c3.y);
    }
}

// ---------------------------------------------------------------------------
// Penalized attention. softmax(P - Z) == softmax(P[k] + prefix_excl_sigmoid).
// 8 warps/block, G=4 queries/warp, 64-key tiles, cp.async double buffering,
// f32x2 packed math in QK (along d) and AV (along the 2 output dims).
// ---------------------------------------------------------------------------
// dynamic smem layout (floats):
//   K bufs  : 2 * 64*68          @ 0
//   V bufs  : 2 * 64*68          @ 2*4352
//   qsh     : 32*68              @ 4*4352
//   esh2    : 8*4*128 (e dup'd)  @ 4*4352 + 2176
#define KV_STRIDE   4352          // 64*68
#define Q_OFF       (4 * KV_STRIDE)
#define E_OFF       (Q_OFF + 2176)
#define ATTN_SMEM_FLOATS (E_OFF + 8 * 4 * 128)

__global__ void __launch_bounds__(256)
attn_kernel(const float* __restrict__ qkv, float* __restrict__ yout)
{
    extern __shared__ __align__(16) float sm[];
    float* Kbuf = sm;                    // [2][64][68]
    float* Vbuf = sm + 2 * KV_STRIDE;    // [2][64][68]
    float* qsh  = sm + Q_OFF;            // [32][68]
    float* esh2 = sm + E_OFF;            // [8*4][128]

    const uint32_t smem_u32 = (uint32_t)__cvta_generic_to_shared(sm);

    const int b     = blockIdx.z;
    const int h     = blockIdx.y;
    const int qbase = blockIdx.x * 32;
    const int w     = threadIdx.x >> 5;
    const int lane  = threadIdx.x & 31;
    const int d0    = 2 * lane;
    const float scale = 0.125f;

    // load the block's 32 q vectors
    #pragma unroll
    for (int i = 0; i < 2; i++) {
        int idx = threadIdx.x + i * 256;
        int qr = idx >> 4, c4 = idx & 15;
        const float* qptr = qkv + (size_t)(b * T_SEQ + qbase + qr) * C3 + h * DHEAD + c4 * 4;
        *(float4*)&qsh[qr * 68 + c4 * 4] = *(const float4*)qptr;
    }

    const float* Kbase = qkv + (size_t)(b * T_SEQ) * C3 + CDIM     + h * DHEAD;
    const float* Vbase = qkv + (size_t)(b * T_SEQ) * C3 + 2 * CDIM + h * DHEAD;
    const int ntiles = (qbase >> 6) + 1;

    // per-thread cp.async coordinates: idx -> (row, c4)
    const int arow = threadIdx.x >> 4;          // base rows: arow, arow+16, +32, +48
    const int ac4  = threadIdx.x & 15;

    // issue tile -> buffer
    auto issue = [&](int tile, int buf) {
        const uint32_t kdst = smem_u32 + (buf * KV_STRIDE) * 4;
        const uint32_t vdst = smem_u32 + (2 * KV_STRIDE + buf * KV_STRIDE) * 4;
        #pragma unroll
        for (int i = 0; i < 4; i++) {
            int r = arow + i * 16;
            size_t gofs = (size_t)(tile * 64 + r) * C3 + ac4 * 4;
            uint32_t sofs = (r * 68 + ac4 * 4) * 4;
            cpasync16(kdst + sofs, Kbase + gofs);
            cpasync16(vdst + sofs, Vbase + gofs);
        }
        asm volatile("cp.async.commit_group;");
    };

    float m[4], denl[4], rtot[4];
    ull y01[4];
    #pragma unroll
    for (int g = 0; g < 4; g++) { m[g] = -1e30f; denl[g] = 0.f; rtot[g] = 0.f; y01[g] = 0ull; }

    issue(0, 0);

    for (int tile = 0; tile < ntiles; tile++) {
        const bool has = (tile + 1 < ntiles);
        if (has) issue(tile + 1, (tile + 1) & 1);
        if (has) asm volatile("cp.async.wait_group 1;");
        else     asm volatile("cp.async.wait_group 0;");
        __syncthreads();

        const float* Kc = Kbuf + (tile & 1) * KV_STRIDE;
        const float* Vc = Vbuf + (tile & 1) * KV_STRIDE;
        const int kt0 = tile << 6;

        // --- QK: packed along d; 2 keys/lane x 4 queries ---
        ull pa0[4] = {0,0,0,0}, pa1[4] = {0,0,0,0};
        {
            const ulonglong2* K0 = (const ulonglong2*)&Kc[lane * 68];
            const ulonglong2* K1 = (const ulonglong2*)&Kc[(lane + 32) * 68];
            #pragma unroll
            for (int d4 = 0; d4 < 16; d4++) {
                ulonglong2 k0 = K0[d4], k1 = K1[d4];
                #pragma unroll
                for (int g = 0; g < 4; g++) {
                    ulonglong2 qv = *(const ulonglong2*)&qsh[(w * 4 + g) * 68 + d4 * 4];
                    fma2(pa0[g], qv.x, k0.x); fma2(pa0[g], qv.y, k0.y);
                    fma2(pa1[g], qv.x, k1.x); fma2(pa1[g], qv.y, k1.y);
                }
            }
        }

        // --- sigmoid prefix scan + online softmax ---
        float alpha_g[4];
        #pragma unroll
        for (int g = 0; g < 4; g++) {
            const int q = qbase + w * 4 + g;
            const int key0 = kt0 + lane;
            const bool v0 = (key0 <= q), v1 = (key0 + 32 <= q);
            float2 u0 = unpack2(pa0[g]); float2 u1 = unpack2(pa1[g]);
            const float P0 = (u0.x + u0.y) * scale;
            const float P1 = (u1.x + u1.y) * scale;
            const float s0 = v0 ? __fdividef(1.0f, 1.0f + __expf(-P0)) : 0.f;
            const float s1 = v1 ? __fdividef(1.0f, 1.0f + __expf(-P1)) : 0.f;

            float sc0 = s0, sc1 = s1;
            #pragma unroll
            for (int off = 1; off < 32; off <<= 1) {
                float t0 = __shfl_up_sync(0xffffffffu, sc0, off);
                float t1 = __shfl_up_sync(0xffffffffu, sc1, off);
                if (lane >= off) { sc0 += t0; sc1 += t1; }
            }
            const float tot0 = __shfl_sync(0xffffffffu, sc0, 31);
            const float tot1 = __shfl_sync(0xffffffffu, sc1, 31);
            const float l0 = v0 ? (P0 + rtot[g] + sc0 - s0)        : -1e30f;
            const float l1 = v1 ? (P1 + rtot[g] + tot0 + sc1 - s1) : -1e30f;
            rtot[g] += tot0 + tot1;

            float cm = fmaxf(l0, l1);
            #pragma unroll
            for (int off = 16; off; off >>= 1)
                cm = fmaxf(cm, __shfl_xor_sync(0xffffffffu, cm, off));
            const float mn = fmaxf(m[g], cm);
            const float al = __expf(m[g] - mn);
            const float e0 = v0 ? __expf(l0 - mn) : 0.f;
            const float e1 = v1 ? __expf(l1 - mn) : 0.f;
            denl[g] = denl[g] * al + e0 + e1;      // per-lane partial denominator
            m[g] = mn;
            alpha_g[g] = al;
            // store e duplicated -> f32x2 operand ready for AV
            float* ep = &esh2[(w * 4 + g) * 128];
            *(float2*)&ep[2 * lane]      = make_float2(e0, e0);
            *(float2*)&ep[64 + 2 * lane] = make_float2(e1, e1);
        }
        __syncwarp();

        // --- AV: packed along the 2 output dims ---
        #pragma unroll
        for (int g = 0; g < 4; g++) y01[g] = mul2(y01[g], pack2(alpha_g[g], alpha_g[g]));
        #pragma unroll
        for (int k4 = 0; k4 < 16; k4++) {
            ull v0 = *(const ull*)&Vc[(k4 * 4 + 0) * 68 + d0];
            ull v1 = *(const ull*)&Vc[(k4 * 4 + 1) * 68 + d0];
            ull v2 = *(const ull*)&Vc[(k4 * 4 + 2) * 68 + d0];
            ull v3 = *(const ull*)&Vc[(k4 * 4 + 3) * 68 + d0];
            #pragma unroll
            for (int g = 0; g < 4; g++) {
                const ulonglong2* E = (const ulonglong2*)&esh2[(w * 4 + g) * 128 + k4 * 8];
                ulonglong2 e01 = E[0], e23 = E[1];
                fma2(y01[g], e01.x, v0); fma2(y01[g], e01.y, v1);
                fma2(y01[g], e23.x, v2); fma2(y01[g], e23.y, v3);
            }
        }
        __syncwarp();
        __syncthreads();   // all warps done with this buffer before next prefetch overwrites
    }

    #pragma unroll
    for (int g = 0; g < 4; g++) {
        float dsum = denl[g];
        #pragma unroll
        for (int off = 16; off; off >>= 1)
            dsum += __shfl_xor_sync(0xffffffffu, dsum, off);
        const float inv = 1.0f / dsum;
        const int q = qbase + w * 4 + g;
        float2 yv = unpack2(y01[g]);
        float* yp = yout + (size_t)(b * T_SEQ + q) * CDIM + h * DHEAD + d0;
        *(float2*)yp = make_float2(yv.x * inv, yv.y * inv);
    }
}

// ---------------------------------------------------------------------------
extern "C" void kernel_launch(void* const* d_in, const int* in_sizes, int n_in,
                              void* d_out, int out_size)
{
    const float* x = nullptr; const float* Wa = nullptr; const float* Wp = nullptr;
    for (int i = 0; i < n_in; i++) {
        if (in_sizes[i] == BATCH * T_SEQ * CDIM)  x  = (const float*)d_in[i];
        else if (in_sizes[i] == C3 * CDIM)        Wa = (const float*)d_in[i];
        else if (in_sizes[i] == CDIM * CDIM)      Wp = (const float*)d_in[i];
    }
    float* out = (float*)d_out;

    void* qkv_p = nullptr; void* y_p = nullptr;
    cudaGetSymbolAddress(&qkv_p, g_qkv);
    cudaGetSymbolAddress(&y_p,   g_y);
    float* qkv = (float*)qkv_p;
    float* y   = (float*)y_p;

    const int ATTN_SMEM = ATTN_SMEM_FLOATS * 4;   // 94,720 B
    cudaFuncSetAttribute(attn_kernel, cudaFuncAttributeMaxDynamicSharedMemorySize, ATTN_SMEM);

    {   // qkv = x @ W_attn^T
        dim3 grid(C3 / 128, MROWS / 128);
        gemm_nt_kernel<<<grid, 256>>>(x, Wa, qkv, MROWS, C3, CDIM);
    }
    {   // penalized attention
        dim3 grid(T_SEQ / 32, HEADS, BATCH);
        attn_kernel<<<grid, 256, ATTN_SMEM>>>(qkv, y);
    }
    {   // out = y @ W_proj^T
        dim3 grid(CDIM / 128, MROWS / 128);
        gemm_nt_kernel<<<grid, 256>>>(y, Wp, out, MROWS, CDIM, CDIM);
    }
}

// round 9
// speedup vs baseline: 1.1127x; 1.1127x over previous
#include <cuda_runtime.h>
#include <math.h>
#include <stdint.h>

#define BATCH   2
#define T_SEQ   2048
#define CDIM    1024
#define HEADS   16
#define DHEAD   64
#define C3      3072
#define MROWS   4096

__device__ float g_qkv[(size_t)MROWS * C3];   // 48 MB
__device__ float g_y  [(size_t)MROWS * CDIM]; // 16 MB

// ---------------------------------------------------------------------------
// NT GEMM: C[M,N] = A[M,K] * B[N,K]^T, 128x128 tile, BK=16, 256 thr, 8x8/thr.
// Double-buffered SMEM + register prefetch, scalar FFMA (proven 634us).
// ---------------------------------------------------------------------------
__global__ void __launch_bounds__(256)
gemm_nt_kernel(const float* __restrict__ A,
               const float* __restrict__ B,
               float* __restrict__ C,
               int M, int N, int K)
{
    const int BK = 16;
    __shared__ __align__(16) float As[2][16][132];
    __shared__ __align__(16) float Bs[2][16][132];

    const int t  = threadIdx.x;
    const int tx = t % 16;
    const int ty = t / 16;
    const int m0 = blockIdx.y * 128;
    const int n0 = blockIdx.x * 128;

    int lrow[2], lc4[2];
    #pragma unroll
    for (int i = 0; i < 2; i++) { int idx = t + i * 256; lrow[i] = idx >> 2; lc4[i] = idx & 3; }

    float acc[8][8];
    #pragma unroll
    for (int i = 0; i < 8; i++)
        #pragma unroll
        for (int j = 0; j < 8; j++) acc[i][j] = 0.f;

    #pragma unroll
    for (int i = 0; i < 2; i++) {
        float4 va = *(const float4*)&A[(size_t)(m0 + lrow[i]) * K + lc4[i] * 4];
        float4 vb = *(const float4*)&B[(size_t)(n0 + lrow[i]) * K + lc4[i] * 4];
        As[0][lc4[i]*4+0][lrow[i]] = va.x; As[0][lc4[i]*4+1][lrow[i]] = va.y;
        As[0][lc4[i]*4+2][lrow[i]] = va.z; As[0][lc4[i]*4+3][lrow[i]] = va.w;
        Bs[0][lc4[i]*4+0][lrow[i]] = vb.x; Bs[0][lc4[i]*4+1][lrow[i]] = vb.y;
        Bs[0][lc4[i]*4+2][lrow[i]] = vb.z; Bs[0][lc4[i]*4+3][lrow[i]] = vb.w;
    }
    __syncthreads();

    const int nt = K / BK;
    for (int tt = 0; tt < nt; tt++) {
        float4 pa[2], pb[2];
        const bool has_next = (tt + 1 < nt);
        if (has_next) {
            const int kn = (tt + 1) * BK;
            #pragma unroll
            for (int i = 0; i < 2; i++) {
                pa[i] = *(const float4*)&A[(size_t)(m0 + lrow[i]) * K + kn + lc4[i] * 4];
                pb[i] = *(const float4*)&B[(size_t)(n0 + lrow[i]) * K + kn + lc4[i] * 4];
            }
        }

        const float (*Ac)[132] = As[tt & 1];
        const float (*Bc)[132] = Bs[tt & 1];
        #pragma unroll
        for (int kk = 0; kk < BK; kk++) {
            float a[8], b[8];
            *(float4*)&a[0] = *(const float4*)&Ac[kk][ty * 8];
            *(float4*)&a[4] = *(const float4*)&Ac[kk][ty * 8 + 4];
            *(float4*)&b[0] = *(const float4*)&Bc[kk][tx * 8];
            *(float4*)&b[4] = *(const float4*)&Bc[kk][tx * 8 + 4];
            #pragma unroll
            for (int i = 0; i < 8; i++)
                #pragma unroll
                for (int j = 0; j < 8; j++)
                    acc[i][j] += a[i] * b[j];
        }

        if (has_next) {
            const int nb = (tt + 1) & 1;
            #pragma unroll
            for (int i = 0; i < 2; i++) {
                As[nb][lc4[i]*4+0][lrow[i]] = pa[i].x; As[nb][lc4[i]*4+1][lrow[i]] = pa[i].y;
                As[nb][lc4[i]*4+2][lrow[i]] = pa[i].z; As[nb][lc4[i]*4+3][lrow[i]] = pa[i].w;
                Bs[nb][lc4[i]*4+0][lrow[i]] = pb[i].x; Bs[nb][lc4[i]*4+1][lrow[i]] = pb[i].y;
                Bs[nb][lc4[i]*4+2][lrow[i]] = pb[i].z; Bs[nb][lc4[i]*4+3][lrow[i]] = pb[i].w;
            }
            __syncthreads();
        }
    }

    #pragma unroll
    for (int i = 0; i < 8; i++) {
        size_t off = (size_t)(m0 + ty * 8 + i) * N + n0 + tx * 8;
        *(float4*)&C[off]     = make_float4(acc[i][0], acc[i][1], acc[i][2], acc[i][3]);
        *(float4*)&C[off + 4] = make_float4(acc[i][4], acc[i][5], acc[i][6], acc[i][7]);
    }
}

// ---------------------------------------------------------------------------
// Penalized attention. softmax(P - Z) == softmax(P[k] + prefix_excl_sigmoid).
// Latency-optimized:
//  - analytic softmax shift m = rtot + 8 (monotone; no max-reduce shuffles;
//    rtot cancels: e = exp(P + excl - tot - 8), alpha = exp(-tot))
//  - lane owns adjacent keys (2*lane, 2*lane+1) via PERMUTED K rows ->
//    one 5-step pair scan per query per 64-key tile (6 shuffles total)
//  - 51.7 KB smem, <=64 regs -> 4 CTAs/SM (8 warps/SMSP) for latency hiding
//  - reversed block order: longest causal blocks first
// smem (floats): Ksh 64*68 | Vsh 64*68 | qsh 32*68 | esh 8*4*64
// ---------------------------------------------------------------------------
#define ATTN_SMEM_FLOATS (4352 + 4352 + 2176 + 2048)

__global__ void __launch_bounds__(256, 4)
attn_kernel(const float* __restrict__ qkv, float* __restrict__ yout)
{
    extern __shared__ __align__(16) float sm[];
    float* Ksh = sm;                 // [64][68], permuted rows
    float* Vsh = sm + 4352;          // [64][68], natural rows
    float* qsh = sm + 8704;          // [32][68]
    float* esh = sm + 10880;         // [8][4][64]

    const int b     = blockIdx.z;
    const int h     = blockIdx.y;
    const int qbase = (int)(gridDim.x - 1 - blockIdx.x) * 32;  // longest first
    const int w     = threadIdx.x >> 5;
    const int lane  = threadIdx.x & 31;
    const int d0    = 2 * lane;
    const float scale = 0.125f;

    // load the block's 32 q vectors
    #pragma unroll
    for (int i = 0; i < 2; i++) {
        int idx = threadIdx.x + i * 256;
        int qr = idx >> 4, c4 = idx & 15;
        const float* qptr = qkv + (size_t)(b * T_SEQ + qbase + qr) * C3 + h * DHEAD + c4 * 4;
        *(float4*)&qsh[qr * 68 + c4 * 4] = *(const float4*)qptr;
    }

    const float* Kbase = qkv + (size_t)(b * T_SEQ) * C3 + CDIM     + h * DHEAD;
    const float* Vbase = qkv + (size_t)(b * T_SEQ) * C3 + 2 * CDIM + h * DHEAD;
    const int ntiles = (qbase >> 6) + 1;

    float denl[4], y0[4], y1[4];
    #pragma unroll
    for (int g = 0; g < 4; g++) { denl[g] = 0.f; y0[g] = 0.f; y1[g] = 0.f; }

    for (int tile = 0; tile < ntiles; tile++) {
        const int kt0 = tile << 6;
        __syncthreads();   // prev-tile consumers done (covers qsh on tile 0)
        #pragma unroll
        for (int i = 0; i < 4; i++) {
            int idx = threadIdx.x + i * 256;
            int r = idx >> 4, c4 = idx & 15;
            size_t gofs = (size_t)(kt0 + r) * C3 + c4 * 4;
            // K permuted: key r -> row r/2 (even) or 32 + r/2 (odd)
            int prow = (r & 1) ? (32 + (r >> 1)) : (r >> 1);
            *(float4*)&Ksh[prow * 68 + c4 * 4] = *(const float4*)&Kbase[gofs];
            *(float4*)&Vsh[r    * 68 + c4 * 4] = *(const float4*)&Vbase[gofs];
        }
        __syncthreads();

        // --- QK: lane owns keys kt0+2*lane (row lane) and kt0+2*lane+1 (row lane+32)
        float p0[4] = {0.f, 0.f, 0.f, 0.f}, p1[4] = {0.f, 0.f, 0.f, 0.f};
        {
            const float4* K0 = (const float4*)&Ksh[lane * 68];
            const float4* K1 = (const float4*)&Ksh[(lane + 32) * 68];
            #pragma unroll
            for (int d4 = 0; d4 < 16; d4++) {
                float4 k0 = K0[d4], k1 = K1[d4];
                #pragma unroll
                for (int g = 0; g < 4; g++) {
                    float4 qv = *(const float4*)&qsh[(w * 4 + g) * 68 + d4 * 4];
                    p0[g] += qv.x * k0.x + qv.y * k0.y + qv.z * k0.z + qv.w * k0.w;
                    p1[g] += qv.x * k1.x + qv.y * k1.y + qv.z * k1.z + qv.w * k1.w;
                }
            }
        }

        // --- sigmoid pair-scan + shifted exp (no max reduction) ---
        float alpha_g[4];
        #pragma unroll
        for (int g = 0; g < 4; g++) {
            const int q    = qbase + w * 4 + g;
            const int key0 = kt0 + 2 * lane;
            const bool v0 = (key0 <= q), v1 = (key0 + 1 <= q);
            const float P0 = p0[g] * scale;
            const float P1 = p1[g] * scale;
            const float s0 = v0 ? __fdividef(1.0f, 1.0f + __expf(-P0)) : 0.f;
            const float s1 = v1 ? __fdividef(1.0f, 1.0f + __expf(-P1)) : 0.f;

            // inclusive scan of pair sums (ordered: pair i covers keys 2i,2i+1)
            float sp = s0 + s1;
            float sc = sp;
            #pragma unroll
            for (int off = 1; off < 32; off <<= 1) {
                float tv = __shfl_up_sync(0xffffffffu, sc, off);
                if (lane >= off) sc += tv;
            }
            const float tot  = __shfl_sync(0xffffffffu, sc, 31);
            const float excl = sc - sp;          // prefix over keys < 2*lane (in tile)

            // e = exp(logit - m_new); m_new = rtot_new + 8, rtot cancels.
            const float c0 = excl - tot - 8.0f;
            const float e0 = v0 ? __expf(P0 + c0)      : 0.f;
            const float e1 = v1 ? __expf(P1 + c0 + s0) : 0.f;
            const float al = __expf(-tot);       // exp(m_old - m_new)
            denl[g] = denl[g] * al + e0 + e1;
            alpha_g[g] = al;
            *(float2*)&esh[(w * 4 + g) * 64 + 2 * lane] = make_float2(e0, e1);
        }
        __syncwarp();

        // --- AV ---
        #pragma unroll
        for (int g = 0; g < 4; g++) { y0[g] *= alpha_g[g]; y1[g] *= alpha_g[g]; }
        #pragma unroll
        for (int k4 = 0; k4 < 16; k4++) {
            float2 v0 = *(const float2*)&Vsh[(k4 * 4 + 0) * 68 + d0];
            float2 v1 = *(const float2*)&Vsh[(k4 * 4 + 1) * 68 + d0];
            float2 v2 = *(const float2*)&Vsh[(k4 * 4 + 2) * 68 + d0];
            float2 v3 = *(const float2*)&Vsh[(k4 * 4 + 3) * 68 + d0];
            #pragma unroll
            for (int g = 0; g < 4; g++) {
                float4 ev = *(const float4*)&esh[(w * 4 + g) * 64 + k4 * 4];
                y0[g] += ev.x * v0.x + ev.y * v1.x + ev.z * v2.x + ev.w * v3.x;
                y1[g] += ev.x * v0.y + ev.y * v1.y + ev.z * v2.y + ev.w * v3.y;
            }
        }
        __syncwarp();
    }

    #pragma unroll
    for (int g = 0; g < 4; g++) {
        float dsum = denl[g];
        #pragma unroll
        for (int off = 16; off; off >>= 1)
            dsum += __shfl_xor_sync(0xffffffffu, dsum, off);
        const float inv = 1.0f / dsum;
        const int q = qbase + w * 4 + g;
        float* yp = yout + (size_t)(b * T_SEQ + q) * CDIM + h * DHEAD + d0;
        *(float2*)yp = make_float2(y0[g] * inv, y1[g] * inv);
    }
}

// ---------------------------------------------------------------------------
extern "C" void kernel_launch(void* const* d_in, const int* in_sizes, int n_in,
                              void* d_out, int out_size)
{
    const float* x = nullptr; const float* Wa = nullptr; const float* Wp = nullptr;
    for (int i = 0; i < n_in; i++) {
        if (in_sizes[i] == BATCH * T_SEQ * CDIM)  x  = (const float*)d_in[i];
        else if (in_sizes[i] == C3 * CDIM)        Wa = (const float*)d_in[i];
        else if (in_sizes[i] == CDIM * CDIM)      Wp = (const float*)d_in[i];
    }
    float* out = (float*)d_out;

    void* qkv_p = nullptr; void* y_p = nullptr;
    cudaGetSymbolAddress(&qkv_p, g_qkv);
    cudaGetSymbolAddress(&y_p,   g_y);
    float* qkv = (float*)qkv_p;
    float* y   = (float*)y_p;

    const int ATTN_SMEM = ATTN_SMEM_FLOATS * 4;   // 51,712 B -> 4 CTAs/SM
    cudaFuncSetAttribute(attn_kernel, cudaFuncAttributeMaxDynamicSharedMemorySize, ATTN_SMEM);

    {   // qkv = x @ W_attn^T
        dim3 grid(C3 / 128, MROWS / 128);
        gemm_nt_kernel<<<grid, 256>>>(x, Wa, qkv, MROWS, C3, CDIM);
    }
    {   // penalized attention
        dim3 grid(T_SEQ / 32, HEADS, BATCH);
        attn_kernel<<<grid, 256, ATTN_SMEM>>>(qkv, y);
    }
    {   // out = y @ W_proj^T
        dim3 grid(CDIM / 128, MROWS / 128);
        gemm_nt_kernel<<<grid, 256>>>(y, Wp, out, MROWS, CDIM, CDIM);
    }
}